// round 5
// baseline (speedup 1.0000x reference)
#include <cuda_runtime.h>
#include <cuda_fp16.h>
#include <cstdint>

// Problem dims
#define FIN   4096
#define FOUT  4096
#define MTOT  4096   // 2 * 2048

// GEMM tiling: CTA computes 128(M) x 256(N), K-chunk = 64
#define BM 128
#define BN 256
#define BK 64
#define KCHUNKS (FIN / BK)   // 64

// SMEM layout (dynamic):
//   [0..4)      TMEM base ptr (written by tcgen05.alloc)
//   [16..32)    mbarriers (2 x u64)
//   [1024 + buf*49152)            A tile (128 rows x 128B) = 16384 B
//   [1024 + buf*49152 + 16384)    B tile (256 rows x 128B) = 32768 B
#define SM_MBAR      16
#define SM_TILE0     1024
#define TILE_STRIDE  49152
#define SMEM_BYTES   (1024 + 2 * TILE_STRIDE)   // 99328

// idesc for tcgen05.mma kind::f16: dtype=F32 (bit4), atype=F16(0), btype=F16(0),
// N/8 at bit17 (256/8=32), M/16 at bit24 (128/16=8), both K-major (no transpose)
#define GEMM_IDESC 0x8400010u

// Per-compilation-pass feature gate: tcgen05 exists only in the arch-specific
// (sm_103a / sm_100a / sm_101a) passes. The plain compute_103 pass the harness
// also builds gets a correct FFMA fallback so ptxas succeeds; at runtime the
// loader exact-matches the sm_103a cubin, so the tcgen05 path is what runs.
#if defined(__CUDA_ARCH__) && \
    (defined(__CUDA_ARCH_FEAT_SM103_ALL) || defined(__CUDA_ARCH_FEAT_SM100_ALL) || \
     defined(__CUDA_ARCH_FEAT_SM101_ALL))
#define HAS_TCGEN05 1
#else
#define HAS_TCGEN05 0
#endif

// fp16 staging buffers (device globals: allocation-free scratch)
__device__ __half g_A[(size_t)MTOT * FIN];   // inp, fp16, row-major [m, k]
__device__ __half g_B[(size_t)FOUT * FIN];   // transformed weight, fp16, [n, k]

// ---------------------------------------------------------------------------
// helpers
// ---------------------------------------------------------------------------
__device__ __forceinline__ uint32_t smem_u32(const void* p) {
    uint32_t a;
    asm("{ .reg .u64 t; cvta.to.shared.u64 t, %1; cvt.u32.u64 %0, t; }"
        : "=r"(a) : "l"(p));
    return a;
}

#define SWZ(x) ((x) ^ (((x) >> 3) & 0x70))

#if HAS_TCGEN05
__device__ __forceinline__ bool elect_one() {
    uint32_t pred;
    asm volatile(
        "{\n\t.reg .pred p;\n\t"
        "elect.sync _|p, 0xFFFFFFFF;\n\t"
        "selp.b32 %0, 1, 0, p;\n\t}"
        : "=r"(pred));
    return pred != 0;
}

// SW128 K-major smem descriptor: layout=SW128(2), version=1 (Blackwell), SBO=64, LBO=1
static constexpr unsigned long long DESC_BASE =
    (2ULL << 61) | (1ULL << 46) | (64ULL << 32) | (1ULL << 16);

__device__ __forceinline__ uint64_t make_desc(uint32_t addr) {
    return DESC_BASE | ((uint64_t)(addr >> 4) & 0x3FFF);
}

__device__ __forceinline__ void wait_parity(uint32_t mbar, int phase) {
    asm volatile(
        "{\n\t.reg .pred P;\n\t"
        "WL%=:\n\t"
        "mbarrier.try_wait.parity.acquire.cta.shared::cta.b64 P, [%0], %1, 0x989680;\n\t"
        "@P bra.uni WD%=;\n\t"
        "bra.uni WL%=;\n\t"
        "WD%=:\n\t}"
        :: "r"(mbar), "r"((uint32_t)phase) : "memory");
}

__device__ __forceinline__ void mma_f16_ss(uint32_t d_tmem, uint64_t a_desc,
                                           uint64_t b_desc, uint32_t en) {
    asm volatile(
        "{\n\t.reg .pred p;\n\t"
        "setp.ne.u32 p, %5, 0;\n\t"
        "tcgen05.mma.cta_group::1.kind::f16 [%0], %1, %2, %3, {%4, %4, %4, %4}, p;\n\t}"
        :: "r"(d_tmem), "l"(a_desc), "l"(b_desc), "r"(GEMM_IDESC),
           "r"(0u), "r"(en)
        : "memory");
}

__device__ __forceinline__ void ldtm_x32(uint32_t* r, uint32_t tmem_addr) {
    asm volatile(
        "tcgen05.ld.sync.aligned.32x32b.x32.b32 "
        "{%0, %1, %2, %3, %4, %5, %6, %7, "
        " %8, %9, %10, %11, %12, %13, %14, %15, "
        " %16, %17, %18, %19, %20, %21, %22, %23, "
        " %24, %25, %26, %27, %28, %29, %30, %31}, [%32];"
        : "=r"(r[0]),  "=r"(r[1]),  "=r"(r[2]),  "=r"(r[3]),
          "=r"(r[4]),  "=r"(r[5]),  "=r"(r[6]),  "=r"(r[7]),
          "=r"(r[8]),  "=r"(r[9]),  "=r"(r[10]), "=r"(r[11]),
          "=r"(r[12]), "=r"(r[13]), "=r"(r[14]), "=r"(r[15]),
          "=r"(r[16]), "=r"(r[17]), "=r"(r[18]), "=r"(r[19]),
          "=r"(r[20]), "=r"(r[21]), "=r"(r[22]), "=r"(r[23]),
          "=r"(r[24]), "=r"(r[25]), "=r"(r[26]), "=r"(r[27]),
          "=r"(r[28]), "=r"(r[29]), "=r"(r[30]), "=r"(r[31])
        : "r"(tmem_addr));
}
#endif  // HAS_TCGEN05

// ---------------------------------------------------------------------------
// Kernel 1: fp32 -> fp16 convert of inp (vectorized)
// ---------------------------------------------------------------------------
__global__ void __launch_bounds__(256) cvt_inp_kernel(const float4* __restrict__ in) {
    int i = blockIdx.x * blockDim.x + threadIdx.x;   // over 16777216/4 vectors
    float4 v = in[i];
    __half2* o = reinterpret_cast<__half2*>(g_A);
    o[2 * i]     = __floats2half2_rn(v.x, v.y);
    o[2 * i + 1] = __floats2half2_rn(v.z, v.w);
}

// ---------------------------------------------------------------------------
// Kernel 2: weight transform.
// W viewed as [4 heads, 1024, 4096]; per-head 3x3 cross-correlation (pad 1)
// + conv_b[h] + sigmoid(sk[h]) * W. Output fp16 into g_B.
// ---------------------------------------------------------------------------
__global__ void __launch_bounds__(256) xform_w_kernel(
    const float* __restrict__ W, const float* __restrict__ cw,
    const float* __restrict__ cb, const float* __restrict__ sk) {
    int row = blockIdx.y;                         // 0..4095 (fout index)
    int c0 = blockIdx.x * 1024 + threadIdx.x * 4; // 4 cols per thread
    int h = row >> 10, r = row & 1023;

    float kk[9];
#pragma unroll
    for (int j = 0; j < 9; ++j) kk[j] = cw[h * 9 + j];
    float bias = cb[h];
    float gate = 1.0f / (1.0f + expf(-sk[h]));

    float acc[4] = {bias, bias, bias, bias};
    const float* base = W + (size_t)(h << 10) * FIN;
#pragma unroll
    for (int dr = -1; dr <= 1; ++dr) {
        int rr = r + dr;
        if (rr < 0 || rr > 1023) continue;
        const float* rp = base + (size_t)rr * FIN;
        float x[6];
        x[0] = (c0 > 0) ? rp[c0 - 1] : 0.f;
        x[1] = rp[c0];     x[2] = rp[c0 + 1];
        x[3] = rp[c0 + 2]; x[4] = rp[c0 + 3];
        x[5] = (c0 + 4 < FIN) ? rp[c0 + 4] : 0.f;
        int kr = (dr + 1) * 3;
#pragma unroll
        for (int j = 0; j < 4; ++j)
            acc[j] += kk[kr] * x[j] + kk[kr + 1] * x[j + 1] + kk[kr + 2] * x[j + 2];
    }
    const float* crow = W + (size_t)row * FIN + c0;
    __half2* o = reinterpret_cast<__half2*>(g_B + (size_t)row * FIN + c0);
    o[0] = __floats2half2_rn(acc[0] + gate * crow[0], acc[1] + gate * crow[1]);
    o[1] = __floats2half2_rn(acc[2] + gate * crow[2], acc[3] + gate * crow[3]);
}

// ---------------------------------------------------------------------------
// Kernel 3: GEMM, 128x256 output tile per CTA.
//   tcgen05 path (sm_103a cubin): double-buffered K=64 chunks, fp32 TMEM acc.
//   fallback path (plain sm_103 cubin, compile-safety): smem-tiled FFMA.
// out[m,n] = sum_k g_A[m,k] * g_B[n,k]
// ---------------------------------------------------------------------------
__global__ void __launch_bounds__(256) gemm_kernel(float* __restrict__ out) {
    extern __shared__ char smem[];
    int tid = threadIdx.x;
    int m0 = blockIdx.y << 7;   // 32 m-tiles
    int n0 = blockIdx.x << 8;   // 16 n-tiles

#if HAS_TCGEN05
    uint32_t sb = smem_u32(smem);
    int wid = tid >> 5, lid = tid & 31;

    if (tid == 0) {
        asm volatile("mbarrier.init.shared.b64 [%0], 1;" :: "r"(sb + SM_MBAR) : "memory");
        asm volatile("mbarrier.init.shared.b64 [%0], 1;" :: "r"(sb + SM_MBAR + 8) : "memory");
    }
    if (wid == 0) {
        asm volatile("tcgen05.alloc.cta_group::1.sync.aligned.shared::cta.b32 [%0], 256;"
                     :: "r"(sb) : "memory");
        asm volatile("tcgen05.relinquish_alloc_permit.cta_group::1.sync.aligned;");
    }
    __syncthreads();
    uint32_t tmem;
    asm volatile("ld.shared.b32 %0, [%1];" : "=r"(tmem) : "r"(sb));

    const uint4* gA = reinterpret_cast<const uint4*>(g_A);  // 512 vecs per row
    const uint4* gB = reinterpret_cast<const uint4*>(g_B);

    int ph[2] = {0, 0};
    for (int i = 0; i < KCHUNKS; ++i) {
        int buf = i & 1;
        uint32_t mb = sb + SM_MBAR + buf * 8;
        if (i >= 2) { wait_parity(mb, ph[buf]); ph[buf] ^= 1; }  // smem buf consumed

        uint32_t sA = sb + SM_TILE0 + buf * TILE_STRIDE;
        uint32_t sB = sA + 16384;
        char* tA = smem + SM_TILE0 + buf * TILE_STRIDE;
        char* tB = tA + 16384;
        int kv = i << 3;  // k0 / 8

        // A tile: 128 rows x 8 x 16B vectors (SW128-swizzled stores)
#pragma unroll
        for (int it = 0; it < 4; ++it) {
            int t = tid + it * 256;
            int r = t >> 3, v = t & 7;
            uint4 val = gA[(size_t)(m0 + r) * 512 + kv + v];
            *reinterpret_cast<uint4*>(tA + SWZ((uint32_t)(r * 128 + v * 16))) = val;
        }
        // B tile: 256 rows x 8 vectors
#pragma unroll
        for (int it = 0; it < 8; ++it) {
            int t = tid + it * 256;
            int r = t >> 3, v = t & 7;
            uint4 val = gB[(size_t)(n0 + r) * 512 + kv + v];
            *reinterpret_cast<uint4*>(tB + SWZ((uint32_t)(r * 128 + v * 16))) = val;
        }
        // generic-proxy stores -> async-proxy (MMA) visibility, then CTA barrier
        asm volatile("fence.proxy.async.shared::cta;" ::: "memory");
        __syncthreads();

        if (wid == 0 && elect_one()) {
            uint64_t ad = make_desc(sA);
            uint64_t bd = make_desc(sB);
#pragma unroll
            for (int ks = 0; ks < 4; ++ks) {   // 4 K=16 steps; +32B per step
                uint32_t en = (i | ks) ? 1u : 0u;
                mma_f16_ss(tmem, ad + ks * 2, bd + ks * 2, en);
            }
            asm volatile(
                "tcgen05.commit.cta_group::1.mbarrier::arrive::one.shared::cluster.b64 [%0];"
                :: "r"(mb) : "memory");
        }
    }

    // last chunk (63) committed on mbar[1]; commit covers all prior MMAs
    wait_parity(sb + SM_MBAR + 8, ph[1]);
    asm volatile("tcgen05.fence::after_thread_sync;" ::: "memory");
    __syncthreads();

    // Epilogue: 8 warps; warp w reads its own subpartition (w&3), column half (w>>2).
    // SMEM 32x33 transpose per warp -> fully coalesced 128B row stores.
    int sp = wid & 3, half = wid >> 2;
    float* scr = reinterpret_cast<float*>(smem + 1024 + wid * 4224);  // 32*33*4
    int col0 = n0 + half * 128;
    int rowb = m0 + sp * 32;
#pragma unroll 1
    for (int cb = 0; cb < 4; ++cb) {
        uint32_t regs[32];
        uint32_t ta = tmem + (uint32_t)(half * 128 + cb * 32) + ((uint32_t)sp << 21);
        ldtm_x32(regs, ta);
        asm volatile("tcgen05.wait::ld.sync.aligned;" ::: "memory");
#pragma unroll
        for (int j = 0; j < 32; ++j) scr[lid * 33 + j] = __uint_as_float(regs[j]);
        __syncwarp();
#pragma unroll 4
        for (int r2 = 0; r2 < 32; ++r2)
            out[(size_t)(rowb + r2) * FOUT + col0 + cb * 32 + lid] = scr[r2 * 33 + lid];
        __syncwarp();
    }
    asm volatile("tcgen05.fence::before_thread_sync;" ::: "memory");
    __syncthreads();
    if (wid == 0) {
        asm volatile("tcgen05.dealloc.cta_group::1.sync.aligned.b32 %0, 256;" :: "r"(tmem));
    }

#else  // ---------- FFMA fallback (plain sm_103 pass; correctness safety net) ----
    // Thread (tm, tn): tm = tid>>4 in [0,16), tn = tid&15 in [0,16).
    // Computes rows m0 + tm*8 .. +8, cols n0 + tn*16 .. +16 (128 outputs).
    __half* tA = reinterpret_cast<__half*>(smem + SM_TILE0);            // 128 x 64
    __half* tB = reinterpret_cast<__half*>(smem + SM_TILE0 + 16384);    // 256 x 64
    int tm = tid >> 4, tn = tid & 15;

    float acc[8][16];
#pragma unroll
    for (int r = 0; r < 8; ++r)
#pragma unroll
        for (int c = 0; c < 16; ++c) acc[r][c] = 0.f;

    const uint4* gA = reinterpret_cast<const uint4*>(g_A);
    const uint4* gB = reinterpret_cast<const uint4*>(g_B);

    for (int i = 0; i < KCHUNKS; ++i) {
        int kv = i << 3;
        __syncthreads();  // previous chunk fully consumed
#pragma unroll
        for (int it = 0; it < 4; ++it) {
            int t = tid + it * 256;
            int r = t >> 3, v = t & 7;
            reinterpret_cast<uint4*>(tA)[(size_t)r * 8 + v] =
                gA[(size_t)(m0 + r) * 512 + kv + v];
        }
#pragma unroll
        for (int it = 0; it < 8; ++it) {
            int t = tid + it * 256;
            int r = t >> 3, v = t & 7;
            reinterpret_cast<uint4*>(tB)[(size_t)r * 8 + v] =
                gB[(size_t)(n0 + r) * 512 + kv + v];
        }
        __syncthreads();

        for (int k = 0; k < BK; ++k) {
            float av[8], bv[16];
#pragma unroll
            for (int r = 0; r < 8; ++r) av[r] = __half2float(tA[(tm * 8 + r) * 64 + k]);
#pragma unroll
            for (int c = 0; c < 16; ++c) bv[c] = __half2float(tB[(tn * 16 + c) * 64 + k]);
#pragma unroll
            for (int r = 0; r < 8; ++r)
#pragma unroll
                for (int c = 0; c < 16; ++c) acc[r][c] += av[r] * bv[c];
        }
    }

#pragma unroll
    for (int r = 0; r < 8; ++r)
#pragma unroll
        for (int c = 0; c < 16; ++c)
            out[(size_t)(m0 + tm * 8 + r) * FOUT + n0 + tn * 16 + c] = acc[r][c];
#endif
}

// ---------------------------------------------------------------------------
extern "C" void kernel_launch(void* const* d_in, const int* in_sizes, int n_in,
                              void* d_out, int out_size) {
    const float* inp = (const float*)d_in[0];  // [2, 2048, 4096]
    const float* W   = (const float*)d_in[1];  // [4096, 4096]
    const float* cw  = (const float*)d_in[2];  // [4, 1, 3, 3]
    const float* cb  = (const float*)d_in[3];  // [4]
    const float* sk  = (const float*)d_in[4];  // [4, 1, 1]
    float* out = (float*)d_out;                // [2, 2048, 4096]

    cudaFuncSetAttribute(gemm_kernel,
                         cudaFuncAttributeMaxDynamicSharedMemorySize, SMEM_BYTES);

    cvt_inp_kernel<<<16384, 256>>>((const float4*)inp);
    xform_w_kernel<<<dim3(4, 4096), 256>>>(W, cw, cb, sk);
    gemm_kernel<<<dim3(16, 32), 256, SMEM_BYTES>>>(out);
}

// round 7
// speedup vs baseline: 1.8049x; 1.8049x over previous
#include <cuda_runtime.h>
#include <cuda_fp16.h>
#include <cstdint>
#include <cstring>

// Problem dims
#define FIN   4096
#define FOUT  4096
#define MTOT  4096   // 2 * 2048

// GEMM tiling: CTA computes 128(M) x 256(N), K-chunk = 64
#define BM 128
#define BN 256
#define BK 64
#define KCHUNKS (FIN / BK)   // 64

#define NSTAGE       4
#define A_BYTES      16384            // 128 rows x 128B
#define B_BYTES      32768            // 256 rows x 128B
#define STAGE_BYTES  (A_BYTES + B_BYTES)   // 49152
// SMEM layout (dynamic):
//   [0..4)     TMEM base ptr (written by tcgen05.alloc)
//   [8..72)    full[s]=8+16s, empty[s]=16+16s  (s=0..3)
//   [72..80)   done mbarrier
//   [1024 + s*49152) stage s: A tile then B tile (1024-aligned for SW128 desc)
#define SM_BAR    8
#define SM_DONE   72
#define SM_TILE0  1024
#define SMEM_BYTES (1024 + NSTAGE * STAGE_BYTES)   // 197632

// idesc for tcgen05.mma kind::f16: dtype=F32 (bit4), atype=F16(0), btype=F16(0),
// N/8 at bit17 (256/8=32), M/16 at bit24 (128/16=8), both K-major
#define GEMM_IDESC 0x8400010u

// tcgen05 exists only in the arch-specific passes; the plain compute_103 pass
// the harness also builds gets a correct FFMA fallback so ptxas succeeds.
// At runtime the loader exact-matches the sm_103a cubin -> tcgen05 path runs.
#if defined(__CUDA_ARCH__) && \
    (defined(__CUDA_ARCH_FEAT_SM103_ALL) || defined(__CUDA_ARCH_FEAT_SM100_ALL) || \
     defined(__CUDA_ARCH_FEAT_SM101_ALL))
#define HAS_TCGEN05 1
#else
#define HAS_TCGEN05 0
#endif

// fp16 staging buffers in chunk-blocked, pre-SW128-swizzled layout:
// g_A: [mtile(32)][chunk(64)][16384B block]   block = swizzled 128x128B image
// g_B: [ntile(16)][chunk(64)][32768B block]   block = swizzled 256x128B image
__device__ __half g_A[(size_t)MTOT * FIN];
__device__ __half g_B[(size_t)FOUT * FIN];

#define SWZ(x) ((x) ^ (((x) >> 3) & 0x70))

// ---------------------------------------------------------------------------
// helpers
// ---------------------------------------------------------------------------
__device__ __forceinline__ uint32_t h2u(__half2 h) {
    uint32_t u;
    memcpy(&u, &h, 4);
    return u;
}

__device__ __forceinline__ uint32_t smem_u32(const void* p) {
    uint32_t a;
    asm("{ .reg .u64 t; cvta.to.shared.u64 t, %1; cvt.u32.u64 %0, t; }"
        : "=r"(a) : "l"(p));
    return a;
}

#if HAS_TCGEN05
__device__ __forceinline__ bool elect_one() {
    uint32_t pred;
    asm volatile(
        "{\n\t.reg .pred p;\n\t"
        "elect.sync _|p, 0xFFFFFFFF;\n\t"
        "selp.b32 %0, 1, 0, p;\n\t}"
        : "=r"(pred));
    return pred != 0;
}

// SW128 K-major smem descriptor: layout=SW128(2), version=1, SBO=64, LBO=1
static constexpr unsigned long long DESC_BASE =
    (2ULL << 61) | (1ULL << 46) | (64ULL << 32) | (1ULL << 16);

__device__ __forceinline__ uint64_t make_desc(uint32_t addr) {
    return DESC_BASE | ((uint64_t)(addr >> 4) & 0x3FFF);
}

__device__ __forceinline__ void wait_parity(uint32_t mbar, int phase) {
    asm volatile(
        "{\n\t.reg .pred P;\n\t"
        "WL%=:\n\t"
        "mbarrier.try_wait.parity.acquire.cta.shared::cta.b64 P, [%0], %1, 0x989680;\n\t"
        "@P bra.uni WD%=;\n\t"
        "bra.uni WL%=;\n\t"
        "WD%=:\n\t}"
        :: "r"(mbar), "r"((uint32_t)phase) : "memory");
}

__device__ __forceinline__ void bulk_g2s(uint32_t dst, const void* src,
                                         uint32_t bytes, uint32_t mbar) {
    asm volatile(
        "cp.async.bulk.shared::cluster.global.mbarrier::complete_tx::bytes "
        "[%0], [%1], %2, [%3];"
        :: "r"(dst), "l"(src), "r"(bytes), "r"(mbar) : "memory");
}

__device__ __forceinline__ void bulk_g2s_mc(uint32_t dst, const void* src,
                                            uint32_t bytes, uint32_t mbar,
                                            uint16_t mask) {
    asm volatile(
        "cp.async.bulk.shared::cluster.global.mbarrier::complete_tx::bytes"
        ".multicast::cluster [%0], [%1], %2, [%3], %4;"
        :: "r"(dst), "l"(src), "r"(bytes), "r"(mbar), "h"(mask) : "memory");
}

__device__ __forceinline__ void mma_f16_ss(uint32_t d_tmem, uint64_t a_desc,
                                           uint64_t b_desc, uint32_t en) {
    asm volatile(
        "{\n\t.reg .pred p;\n\t"
        "setp.ne.u32 p, %5, 0;\n\t"
        "tcgen05.mma.cta_group::1.kind::f16 [%0], %1, %2, %3, {%4, %4, %4, %4}, p;\n\t}"
        :: "r"(d_tmem), "l"(a_desc), "l"(b_desc), "r"(GEMM_IDESC),
           "r"(0u), "r"(en)
        : "memory");
}

__device__ __forceinline__ void ldtm_x32(uint32_t* r, uint32_t tmem_addr) {
    asm volatile(
        "tcgen05.ld.sync.aligned.32x32b.x32.b32 "
        "{%0, %1, %2, %3, %4, %5, %6, %7, "
        " %8, %9, %10, %11, %12, %13, %14, %15, "
        " %16, %17, %18, %19, %20, %21, %22, %23, "
        " %24, %25, %26, %27, %28, %29, %30, %31}, [%32];"
        : "=r"(r[0]),  "=r"(r[1]),  "=r"(r[2]),  "=r"(r[3]),
          "=r"(r[4]),  "=r"(r[5]),  "=r"(r[6]),  "=r"(r[7]),
          "=r"(r[8]),  "=r"(r[9]),  "=r"(r[10]), "=r"(r[11]),
          "=r"(r[12]), "=r"(r[13]), "=r"(r[14]), "=r"(r[15]),
          "=r"(r[16]), "=r"(r[17]), "=r"(r[18]), "=r"(r[19]),
          "=r"(r[20]), "=r"(r[21]), "=r"(r[22]), "=r"(r[23]),
          "=r"(r[24]), "=r"(r[25]), "=r"(r[26]), "=r"(r[27]),
          "=r"(r[28]), "=r"(r[29]), "=r"(r[30]), "=r"(r[31])
        : "r"(tmem_addr));
}
#endif  // HAS_TCGEN05

// ---------------------------------------------------------------------------
// Kernel 1: fp32 -> fp16 convert of inp, writing chunk-blocked swizzled g_A.
// One thread = one 16B output vector (8 k-values).
// ---------------------------------------------------------------------------
__global__ void __launch_bounds__(256) cvt_inp_kernel(const float4* __restrict__ in) {
    int i = blockIdx.x * 256 + threadIdx.x;     // 0 .. 2M-1
    int m = i >> 9, kv = i & 511;               // kv = 16B-vector index in row
    float4 v0 = in[(size_t)m * 1024 + kv * 2];
    float4 v1 = in[(size_t)m * 1024 + kv * 2 + 1];
    uint4 u;
    u.x = h2u(__floats2half2_rn(v0.x, v0.y));
    u.y = h2u(__floats2half2_rn(v0.z, v0.w));
    u.z = h2u(__floats2half2_rn(v1.x, v1.y));
    u.w = h2u(__floats2half2_rn(v1.z, v1.w));
    uint32_t blk = (uint32_t)(m >> 7) * 64 + (kv >> 3);
    uint32_t off = SWZ((uint32_t)(m & 127) * 128 + (kv & 7) * 16);
    *reinterpret_cast<uint4*>(reinterpret_cast<char*>(g_A) +
                              (size_t)blk * A_BYTES + off) = u;
}

// ---------------------------------------------------------------------------
// Kernel 2: weight transform -> chunk-blocked swizzled g_B.
// W viewed as [4 heads, 1024, 4096]; per-head 3x3 conv (pad 1) + bias
// + sigmoid(sk)*W. One thread = 8 k-values = one 16B output vector.
// ---------------------------------------------------------------------------
__global__ void __launch_bounds__(512) xform_w_kernel(
    const float* __restrict__ W, const float* __restrict__ cw,
    const float* __restrict__ cb, const float* __restrict__ sk) {
    int row = blockIdx.x;          // fout index 0..4095
    int tid = threadIdx.x;         // 0..511
    int c0 = tid * 8;
    int h = row >> 10, r = row & 1023;

    float kk[9];
#pragma unroll
    for (int j = 0; j < 9; ++j) kk[j] = cw[h * 9 + j];
    float bias = cb[h];
    float gate = 1.0f / (1.0f + expf(-sk[h]));

    float acc[8], cen[8];
#pragma unroll
    for (int j = 0; j < 8; ++j) acc[j] = bias;

    const float* base = W + (size_t)(h << 10) * FIN;
#pragma unroll
    for (int dr = -1; dr <= 1; ++dr) {
        int rr = r + dr;
        if (rr < 0 || rr > 1023) continue;
        const float* rp = base + (size_t)rr * FIN;
        float x[10];
        x[0] = (c0 > 0) ? rp[c0 - 1] : 0.f;
        float4 a = *reinterpret_cast<const float4*>(rp + c0);
        float4 b = *reinterpret_cast<const float4*>(rp + c0 + 4);
        x[1] = a.x; x[2] = a.y; x[3] = a.z; x[4] = a.w;
        x[5] = b.x; x[6] = b.y; x[7] = b.z; x[8] = b.w;
        x[9] = (c0 + 8 < FIN) ? rp[c0 + 8] : 0.f;
        if (dr == 0) {
#pragma unroll
            for (int j = 0; j < 8; ++j) cen[j] = x[j + 1];
        }
        int kr = (dr + 1) * 3;
#pragma unroll
        for (int j = 0; j < 8; ++j)
            acc[j] += kk[kr] * x[j] + kk[kr + 1] * x[j + 1] + kk[kr + 2] * x[j + 2];
    }

    uint4 u;
    u.x = h2u(__floats2half2_rn(acc[0] + gate * cen[0], acc[1] + gate * cen[1]));
    u.y = h2u(__floats2half2_rn(acc[2] + gate * cen[2], acc[3] + gate * cen[3]));
    u.z = h2u(__floats2half2_rn(acc[4] + gate * cen[4], acc[5] + gate * cen[5]));
    u.w = h2u(__floats2half2_rn(acc[6] + gate * cen[6], acc[7] + gate * cen[7]));
    uint32_t blk = (uint32_t)(row >> 8) * 64 + (tid >> 3);
    uint32_t off = SWZ((uint32_t)(row & 255) * 128 + (tid & 7) * 16);
    *reinterpret_cast<uint4*>(reinterpret_cast<char*>(g_B) +
                              (size_t)blk * B_BYTES + off) = u;
}

// ---------------------------------------------------------------------------
// Kernel 3: tcgen05 GEMM. 128x256 tile / CTA, 4-stage cp.async.bulk pipeline,
// 2-CTA cluster (same n-tile) with multicast B and multicast stage-free commit.
// out[m,n] = sum_k g_A[m,k] * g_B[n,k], fp32 accumulate in TMEM.
// ---------------------------------------------------------------------------
__global__ void __launch_bounds__(256, 1) __cluster_dims__(1, 2, 1)
gemm_kernel(float* __restrict__ out) {
    extern __shared__ char smem[];
    int tid = threadIdx.x;
    int m0 = blockIdx.y << 7;   // 32 m-tiles (cluster pairs adjacent m)
    int n0 = blockIdx.x << 8;   // 16 n-tiles (shared within cluster)

#if HAS_TCGEN05
    uint32_t sb = smem_u32(smem);
    int wid = tid >> 5, lid = tid & 31;
    uint32_t rank;
    asm("mov.u32 %0, %%cluster_ctarank;" : "=r"(rank));

    if (tid == 0) {
#pragma unroll
        for (int s = 0; s < NSTAGE; ++s) {
            asm volatile("mbarrier.init.shared.b64 [%0], 1;"
                         :: "r"(sb + SM_BAR + s * 16) : "memory");       // full
            asm volatile("mbarrier.init.shared.b64 [%0], 2;"
                         :: "r"(sb + SM_BAR + s * 16 + 8) : "memory");   // empty
        }
        asm volatile("mbarrier.init.shared.b64 [%0], 1;"
                     :: "r"(sb + SM_DONE) : "memory");
    }
    if (wid == 0) {
        asm volatile("tcgen05.alloc.cta_group::1.sync.aligned.shared::cta.b32 [%0], 256;"
                     :: "r"(sb) : "memory");
        asm volatile("tcgen05.relinquish_alloc_permit.cta_group::1.sync.aligned;");
    }
    __syncthreads();
    // both CTAs' barriers must exist before any multicast targets the peer
    asm volatile("barrier.cluster.arrive.aligned;" ::: "memory");
    asm volatile("barrier.cluster.wait.aligned;" ::: "memory");

    uint32_t tmem;
    asm volatile("ld.shared.b32 %0, [%1];" : "=r"(tmem) : "r"(sb));

    if (wid == 0 && elect_one()) {
        // ---- producer: one thread, bulk copies only ----
        const char* gAb = reinterpret_cast<const char*>(g_A) +
                          (size_t)(m0 >> 7) * 64 * A_BYTES;
        const char* gBb = reinterpret_cast<const char*>(g_B) +
                          (size_t)(n0 >> 8) * 64 * B_BYTES;
        int eph[NSTAGE] = {0, 0, 0, 0};
        for (int i = 0; i < KCHUNKS; ++i) {
            int s = i & (NSTAGE - 1);
            uint32_t full = sb + SM_BAR + s * 16;
            if (i >= NSTAGE) { wait_parity(full + 8, eph[s]); eph[s] ^= 1; }
            uint32_t dA = sb + SM_TILE0 + s * STAGE_BYTES;
            asm volatile("mbarrier.arrive.expect_tx.shared.b64 _, [%0], %1;"
                         :: "r"(full), "r"((uint32_t)STAGE_BYTES) : "memory");
            bulk_g2s(dA, gAb + (size_t)i * A_BYTES, A_BYTES, full);
            if (rank == 0)  // B shared across the pair: load once, multicast
                bulk_g2s_mc(dA + A_BYTES, gBb + (size_t)i * B_BYTES,
                            B_BYTES, full, 0x3);
        }
    } else if (wid == 1 && elect_one()) {
        // ---- consumer: one thread, MMA issue ----
        int fph[NSTAGE] = {0, 0, 0, 0};
        for (int i = 0; i < KCHUNKS; ++i) {
            int s = i & (NSTAGE - 1);
            uint32_t full = sb + SM_BAR + s * 16;
            wait_parity(full, fph[s]); fph[s] ^= 1;
            uint32_t sA = sb + SM_TILE0 + s * STAGE_BYTES;
            uint64_t ad = make_desc(sA);
            uint64_t bd = make_desc(sA + A_BYTES);
#pragma unroll
            for (int ks = 0; ks < 4; ++ks)     // 4 K=16 steps; +32B per step
                mma_f16_ss(tmem, ad + ks * 2, bd + ks * 2, (uint32_t)(i | ks));
            if (i < KCHUNKS - 1) {
                // free this stage in BOTH CTAs once the MMAs complete
                asm volatile(
                    "tcgen05.commit.cta_group::1.mbarrier::arrive::one."
                    "shared::cluster.multicast::cluster.b64 [%0], %1;"
                    :: "r"(full + 8), "h"((uint16_t)0x3) : "memory");
            } else {
                // final chunk -> local done barrier (single-use, parity 0).
                // accumulator-chain ordering => all prior MMAs complete too.
                asm volatile(
                    "tcgen05.commit.cta_group::1.mbarrier::arrive::one."
                    "shared::cluster.b64 [%0];"
                    :: "r"(sb + SM_DONE) : "memory");
            }
        }
    }

    // all 8 warps: wait for full accumulation
    wait_parity(sb + SM_DONE, 0);
    asm volatile("tcgen05.fence::after_thread_sync;" ::: "memory");
    __syncthreads();

    // Epilogue: warp w reads subpartition (w&3), column half (w>>2).
    // SMEM 32x33 transpose per warp -> coalesced 128B row stores.
    int sp = wid & 3, half = wid >> 2;
    float* scr = reinterpret_cast<float*>(smem + 1024 + wid * 4224);  // 32*33*4
    int col0 = n0 + half * 128;
    int rowb = m0 + sp * 32;
#pragma unroll 1
    for (int cb = 0; cb < 4; ++cb) {
        uint32_t regs[32];
        uint32_t ta = tmem + (uint32_t)(half * 128 + cb * 32) + ((uint32_t)sp << 21);
        ldtm_x32(regs, ta);
        asm volatile("tcgen05.wait::ld.sync.aligned;" ::: "memory");
#pragma unroll
        for (int j = 0; j < 32; ++j) scr[lid * 33 + j] = __uint_as_float(regs[j]);
        __syncwarp();
#pragma unroll 4
        for (int r2 = 0; r2 < 32; ++r2)
            out[(size_t)(rowb + r2) * FOUT + col0 + cb * 32 + lid] = scr[r2 * 33 + lid];
        __syncwarp();
    }
    asm volatile("tcgen05.fence::before_thread_sync;" ::: "memory");
    __syncthreads();
    if (wid == 0) {
        asm volatile("tcgen05.dealloc.cta_group::1.sync.aligned.b32 %0, 256;" :: "r"(tmem));
    }
    // no CTA exits while peer multicasts/commits could still target it
    asm volatile("barrier.cluster.arrive.aligned;" ::: "memory");
    asm volatile("barrier.cluster.wait.aligned;" ::: "memory");

#else  // ---------- FFMA fallback (plain sm_103 pass; correctness safety net) ----
    __half* tA = reinterpret_cast<__half*>(smem + SM_TILE0);            // 128 x 64
    __half* tB = reinterpret_cast<__half*>(smem + SM_TILE0 + A_BYTES);  // 256 x 64
    int tm = tid >> 4, tn = tid & 15;

    float acc[8][16];
#pragma unroll
    for (int r = 0; r < 8; ++r)
#pragma unroll
        for (int c = 0; c < 16; ++c) acc[r][c] = 0.f;

    const uint4* gA4 = reinterpret_cast<const uint4*>(g_A);
    const uint4* gB4 = reinterpret_cast<const uint4*>(g_B);

    for (int i = 0; i < KCHUNKS; ++i) {
        __syncthreads();
        uint32_t blkA = (uint32_t)(m0 >> 7) * 64 + i;
        uint32_t blkB = (uint32_t)(n0 >> 8) * 64 + i;
#pragma unroll
        for (int it = 0; it < 4; ++it) {
            int t = tid + it * 256;
            int r = t >> 3, v = t & 7;
            reinterpret_cast<uint4*>(tA)[r * 8 + v] =
                gA4[(size_t)blkA * 1024 + (SWZ((uint32_t)(r * 128 + v * 16)) >> 4)];
        }
#pragma unroll
        for (int it = 0; it < 8; ++it) {
            int t = tid + it * 256;
            int r = t >> 3, v = t & 7;
            reinterpret_cast<uint4*>(tB)[r * 8 + v] =
                gB4[(size_t)blkB * 2048 + (SWZ((uint32_t)(r * 128 + v * 16)) >> 4)];
        }
        __syncthreads();

        for (int k = 0; k < BK; ++k) {
            float av[8], bv[16];
#pragma unroll
            for (int r = 0; r < 8; ++r) av[r] = __half2float(tA[(tm * 8 + r) * 64 + k]);
#pragma unroll
            for (int c = 0; c < 16; ++c) bv[c] = __half2float(tB[(tn * 16 + c) * 64 + k]);
#pragma unroll
            for (int r = 0; r < 8; ++r)
#pragma unroll
                for (int c = 0; c < 16; ++c) acc[r][c] += av[r] * bv[c];
        }
    }

#pragma unroll
    for (int r = 0; r < 8; ++r)
#pragma unroll
        for (int c = 0; c < 16; ++c)
            out[(size_t)(m0 + tm * 8 + r) * FOUT + n0 + tn * 16 + c] = acc[r][c];
#endif
}

// ---------------------------------------------------------------------------
extern "C" void kernel_launch(void* const* d_in, const int* in_sizes, int n_in,
                              void* d_out, int out_size) {
    const float* inp = (const float*)d_in[0];  // [2, 2048, 4096]
    const float* W   = (const float*)d_in[1];  // [4096, 4096]
    const float* cw  = (const float*)d_in[2];  // [4, 1, 3, 3]
    const float* cb  = (const float*)d_in[3];  // [4]
    const float* sk  = (const float*)d_in[4];  // [4, 1, 1]
    float* out = (float*)d_out;                // [2, 2048, 4096]

    cudaFuncSetAttribute(gemm_kernel,
                         cudaFuncAttributeMaxDynamicSharedMemorySize, SMEM_BYTES);

    cvt_inp_kernel<<<8192, 256>>>((const float4*)inp);
    xform_w_kernel<<<4096, 512>>>(W, cw, cb, sk);
    gemm_kernel<<<dim3(16, 32), 256, SMEM_BYTES>>>(out);
}